// round 10
// baseline (speedup 1.0000x reference)
#include <cuda_runtime.h>

// AutoregressiveBisectionInverter — closed-form inversion, R6 (re-bench; prior
// submission hit an infra failure before running).
//
// W strictly lower triangular => bisected function is linear in x_i:
//   x_i = (y_i - sum_{j<i} W[i,j] tanh(x_j)) / softplus(a_i)
// Pre-scale Wsh[i][j] = -W[i,j]/softplus(a_i), y'_i = y_i/softplus(a_i):
//   x_i = y'_i + sum_{j<i} Wsh[i,j] * tanh(x_j)
//
// One warp per batch row; lane l accumulates dims {l, l+32}. Wsh[l][j]=0 for
// j>=l, so lane l's accumulator FREEZES at x_l -> final acc IS the output.
//
// R6: single-barrier prolog. Thread t stages one half-row of W (row t>>1),
// computing 1/softplus(a[row]) itself (no smem invs, no first sync). acc init
// and chunk-0 shfls hoisted before the barrier. 128 thr / 128 blocks.

#define AD 64
#define AB 512
#define ROWS_PER_BLOCK 4
#define NTHREADS (32 * ROWS_PER_BLOCK)
#define WSTRIDE 68

__device__ __forceinline__ float tanh_fast(float x) {
    float r;
    asm("tanh.approx.f32 %0, %1;" : "=f"(r) : "f"(x));
    return r;
}

__device__ __forceinline__ float inv_softplus(float x) {
    // 1 / log(1 + e^x), MUFU-only; x in [0.5, 1.5].
    return __fdividef(1.0f, __logf(1.0f + __expf(x)));
}

__global__ __launch_bounds__(NTHREADS, 1)
void arbi_kernel(const float* __restrict__ y,
                 const float* __restrict__ a,
                 const float* __restrict__ W,
                 float* __restrict__ out)
{
    __shared__ __align__(16) float Wsh[AD * WSTRIDE];

    const int tid  = threadIdx.x;
    const int lane = tid & 31;
    const int warp = tid >> 5;
    const int row  = blockIdx.x * ROWS_PER_BLOCK + warp;

    // ---- Issue ALL independent global loads up front (one round trip) ----
    const float* yr = y + row * AD;
    const float yv0 = yr[lane];
    const float yv1 = yr[lane + 32];

    // Thread t stages row (t>>1), half (t&1): 8 float4 = 128 bytes.
    const int wrow  = tid >> 1;
    const int whalf = tid & 1;
    const float4* Wr4 = (const float4*)(W + wrow * AD) + whalf * 8;
    float4 wv[8];
    #pragma unroll
    for (int k = 0; k < 8; ++k) wv[k] = Wr4[k];

    const float a_row = a[wrow];
    const float a_l0  = a[lane];
    const float a_l1  = a[lane + 32];

    // ---- Per-thread softplus inverses (no smem, no extra sync) ----
    const float inv_row = inv_softplus(a_row);
    const float inv_l0  = inv_softplus(a_l0);
    const float inv_l1  = inv_softplus(a_l1);

    // ---- Scale + stage this thread's half-row ----
    {
        const float sc = -inv_row;
        float* dst = &Wsh[wrow * WSTRIDE + whalf * 32];
        #pragma unroll
        for (int k = 0; k < 8; ++k) {
            float4 s;
            s.x = wv[k].x * sc; s.y = wv[k].y * sc;
            s.z = wv[k].z * sc; s.w = wv[k].w * sc;
            *(float4*)&dst[k * 4] = s;
        }
    }

    // ---- Accumulators (double as outputs) + chunk-0 partials, pre-barrier ----
    float acc0 = yv0 * inv_l0;
    float acc1 = yv1 * inv_l1;

    float b0 = __shfl_sync(0xffffffffu, acc0, 0);
    float b1 = __shfl_sync(0xffffffffu, acc0, 1);
    float b2 = __shfl_sync(0xffffffffu, acc0, 2);
    float b3 = __shfl_sync(0xffffffffu, acc0, 3);

    __syncthreads();

    #pragma unroll
    for (int c = 0; c < 16; ++c) {
        const int j = 4 * c;

        // Lane-uniform diag-band weights (broadcast LDS; pairs as v2).
        const float  w10    = Wsh[(j + 1) * WSTRIDE + j];
        const float2 w20_21 = *(const float2*)&Wsh[(j + 2) * WSTRIDE + j];
        const float2 w30_31 = *(const float2*)&Wsh[(j + 3) * WSTRIDE + j];
        const float  w32    = Wsh[(j + 3) * WSTRIDE + j + 2];
        float2 w4 = {0.f, 0.f}, w5 = {0.f, 0.f};
        float2 w6 = {0.f, 0.f}, w7 = {0.f, 0.f};
        if (c < 15) {
            w4 = *(const float2*)&Wsh[(j + 4) * WSTRIDE + j + 2];
            w5 = *(const float2*)&Wsh[(j + 5) * WSTRIDE + j + 2];
            w6 = *(const float2*)&Wsh[(j + 6) * WSTRIDE + j + 2];
            w7 = *(const float2*)&Wsh[(j + 7) * WSTRIDE + j + 2];
        }
        // Per-lane acc-update weights for this chunk's 4 columns (LDS.128).
        const float4 wla = *(const float4*)&Wsh[lane * WSTRIDE + j];
        const float4 wlb = *(const float4*)&Wsh[(lane + 32) * WSTRIDE + j];

        // ---- dim j ----
        const float t0 = tanh_fast(b0);

        // ---- dim j+1 ----
        const float x1 = fmaf(w10, t0, b1);
        const float t1 = tanh_fast(x1);

        acc0 = fmaf(wla.x, t0, acc0);
        acc1 = fmaf(wlb.x, t0, acc1);
        acc0 = fmaf(wla.y, t1, acc0);
        acc1 = fmaf(wlb.y, t1, acc1);

        // Early shfl of next chunk's partials (contain t_{<=j+1}); missing
        // t_{j+2}, t_{j+3} replayed below on all lanes.
        float bp0 = 0.f, bp1 = 0.f, bp2 = 0.f, bp3 = 0.f;
        if (c < 15) {
            const float src = (j + 4 < 32) ? acc0 : acc1;
            bp0 = __shfl_sync(0xffffffffu, src, (j + 4) & 31);
            bp1 = __shfl_sync(0xffffffffu, src, (j + 5) & 31);
            bp2 = __shfl_sync(0xffffffffu, src, (j + 6) & 31);
            bp3 = __shfl_sync(0xffffffffu, src, (j + 7) & 31);
        }

        // ---- dim j+2 ----
        const float x2 = fmaf(w20_21.y, t1, fmaf(w20_21.x, t0, b2));
        const float t2 = tanh_fast(x2);

        acc0 = fmaf(wla.z, t2, acc0);
        acc1 = fmaf(wlb.z, t2, acc1);

        // ---- dim j+3 ----
        const float x3 = fmaf(w32, t2,
                        fmaf(w30_31.y, t1, fmaf(w30_31.x, t0, b3)));
        const float t3 = tanh_fast(x3);

        acc0 = fmaf(wla.w, t3, acc0);
        acc1 = fmaf(wlb.w, t3, acc1);

        // Replay t_{j+2}, t_{j+3} into the early-shfl'd partials.
        if (c < 15) {
            b0 = fmaf(w4.y, t3, fmaf(w4.x, t2, bp0));
            b1 = fmaf(w5.y, t3, fmaf(w5.x, t2, bp1));
            b2 = fmaf(w6.y, t3, fmaf(w6.x, t2, bp2));
            b3 = fmaf(w7.y, t3, fmaf(w7.x, t2, bp3));
        }
    }

    // Final accumulators are the solution (rows frozen past their own dim).
    out[row * AD + lane]      = acc0;
    out[row * AD + lane + 32] = acc1;
}

extern "C" void kernel_launch(void* const* d_in, const int* in_sizes, int n_in,
                              void* d_out, int out_size)
{
    const float* y = (const float*)d_in[0];   // (512, 64)
    const float* a = (const float*)d_in[1];   // (64,)
    const float* W = (const float*)d_in[2];   // (64, 64)
    float* out = (float*)d_out;               // (512, 64)

    arbi_kernel<<<AB / ROWS_PER_BLOCK, NTHREADS>>>(y, a, W, out);
}

// round 11
// speedup vs baseline: 1.1256x; 1.1256x over previous
#include <cuda_runtime.h>

// AutoregressiveBisectionInverter — closed-form inversion, R11.
// = R4 prolog (best bench) + R5 loop body (best ncu) + mid-loop out0 store.
//
// W strictly lower triangular => bisected function is linear in x_i:
//   x_i = (y_i - sum_{j<i} W[i,j] tanh(x_j)) / softplus(a_i)
// Pre-scale Wsh[i][j] = -W[i,j]/softplus(a_i), y'_i = y_i/softplus(a_i):
//   x_i = y'_i + sum_{j<i} Wsh[i,j] * tanh(x_j)
//
// One warp per batch row; lane l accumulates dims {l, l+32}. Wsh[l][j]=0 for
// j>=l  =>  lane l's accumulator FREEZES at x_l; final acc IS the output, and
// acc0 (dims 0..31) is final after column 31 -> stored at mid-loop.

#define AD 64
#define AB 512
#define ROWS_PER_BLOCK 4
#define NTHREADS (32 * ROWS_PER_BLOCK)
#define WSTRIDE 68

__device__ __forceinline__ float tanh_fast(float x) {
    float r;
    asm("tanh.approx.f32 %0, %1;" : "=f"(r) : "f"(x));
    return r;
}

__global__ __launch_bounds__(NTHREADS, 1)
void arbi_kernel(const float* __restrict__ y,
                 const float* __restrict__ a,
                 const float* __restrict__ W,
                 float* __restrict__ out)
{
    __shared__ float invs_sh[AD];
    __shared__ __align__(16) float Wsh[AD * WSTRIDE];

    const int tid  = threadIdx.x;
    const int lane = tid & 31;
    const int warp = tid >> 5;
    const int row  = blockIdx.x * ROWS_PER_BLOCK + warp;

    // ---- Issue ALL independent global loads up front (one round trip) ----
    const float* yr = y + row * AD;
    const float yv0 = yr[lane];
    const float yv1 = yr[lane + 32];

    const float4* W4 = (const float4*)W;
    float4 wv[8];
    #pragma unroll
    for (int k = 0; k < 8; ++k) {
        wv[k] = W4[tid + NTHREADS * k];      // raw W; scaled after sync
    }

    float av = 0.0f;
    if (tid < AD) av = a[tid];

    // 1/softplus(a) via MUFU-only ops (a in [0.5,1.5], no overflow).
    if (tid < AD) {
        invs_sh[tid] = __fdividef(1.0f, __logf(1.0f + __expf(av)));
    }
    __syncthreads();

    // ---- Scale staged W in registers, store to padded smem (stride 68) ----
    #pragma unroll
    for (int k = 0; k < 8; ++k) {
        const int idx = tid + NTHREADS * k;  // float4 index; 16 per row
        const int r   = idx >> 4;
        const int c4  = idx & 15;
        const float sc = -invs_sh[r];
        float4 s;
        s.x = wv[k].x * sc; s.y = wv[k].y * sc;
        s.z = wv[k].z * sc; s.w = wv[k].w * sc;
        *(float4*)&Wsh[r * WSTRIDE + c4 * 4] = s;
    }
    __syncthreads();

    // ---- Accumulators double as outputs (rows freeze past their own dim) ----
    float acc0 = yv0 * invs_sh[lane];
    float acc1 = yv1 * invs_sh[lane + 32];

    // Chunk 0 partials: dims 0..3 live in acc0 of lanes 0..3.
    float b0 = __shfl_sync(0xffffffffu, acc0, 0);
    float b1 = __shfl_sync(0xffffffffu, acc0, 1);
    float b2 = __shfl_sync(0xffffffffu, acc0, 2);
    float b3 = __shfl_sync(0xffffffffu, acc0, 3);

    #pragma unroll
    for (int c = 0; c < 16; ++c) {
        const int j = 4 * c;

        // Lane-uniform diag-band weights (broadcast LDS; pairs as v2).
        const float  w10    = Wsh[(j + 1) * WSTRIDE + j];
        const float2 w20_21 = *(const float2*)&Wsh[(j + 2) * WSTRIDE + j];
        const float2 w30_31 = *(const float2*)&Wsh[(j + 3) * WSTRIDE + j];
        const float  w32    = Wsh[(j + 3) * WSTRIDE + j + 2];
        float2 w4 = {0.f, 0.f}, w5 = {0.f, 0.f};
        float2 w6 = {0.f, 0.f}, w7 = {0.f, 0.f};
        if (c < 15) {
            w4 = *(const float2*)&Wsh[(j + 4) * WSTRIDE + j + 2];
            w5 = *(const float2*)&Wsh[(j + 5) * WSTRIDE + j + 2];
            w6 = *(const float2*)&Wsh[(j + 6) * WSTRIDE + j + 2];
            w7 = *(const float2*)&Wsh[(j + 7) * WSTRIDE + j + 2];
        }
        // Per-lane acc-update weights for this chunk's 4 columns (LDS.128).
        const float4 wla = *(const float4*)&Wsh[lane * WSTRIDE + j];
        const float4 wlb = *(const float4*)&Wsh[(lane + 32) * WSTRIDE + j];

        // ---- dim j ----
        const float t0 = tanh_fast(b0);

        // ---- dim j+1 ----
        const float x1 = fmaf(w10, t0, b1);
        const float t1 = tanh_fast(x1);

        acc0 = fmaf(wla.x, t0, acc0);
        acc1 = fmaf(wlb.x, t0, acc1);
        acc0 = fmaf(wla.y, t1, acc0);
        acc1 = fmaf(wlb.y, t1, acc1);

        // Early shfl of next chunk's partials (contain t_{<=j+1}); missing
        // t_{j+2}, t_{j+3} replayed below on all lanes.
        float bp0 = 0.f, bp1 = 0.f, bp2 = 0.f, bp3 = 0.f;
        if (c < 15) {
            const float src = (j + 4 < 32) ? acc0 : acc1;
            bp0 = __shfl_sync(0xffffffffu, src, (j + 4) & 31);
            bp1 = __shfl_sync(0xffffffffu, src, (j + 5) & 31);
            bp2 = __shfl_sync(0xffffffffu, src, (j + 6) & 31);
            bp3 = __shfl_sync(0xffffffffu, src, (j + 7) & 31);
        }

        // ---- dim j+2 ----
        const float x2 = fmaf(w20_21.y, t1, fmaf(w20_21.x, t0, b2));
        const float t2 = tanh_fast(x2);

        acc0 = fmaf(wla.z, t2, acc0);
        acc1 = fmaf(wlb.z, t2, acc1);

        // ---- dim j+3 ----
        const float x3 = fmaf(w32, t2,
                        fmaf(w30_31.y, t1, fmaf(w30_31.x, t0, b3)));
        const float t3 = tanh_fast(x3);

        acc0 = fmaf(wla.w, t3, acc0);
        acc1 = fmaf(wlb.w, t3, acc1);

        // Replay t_{j+2}, t_{j+3} into the early-shfl'd partials.
        if (c < 15) {
            b0 = fmaf(w4.y, t3, fmaf(w4.x, t2, bp0));
            b1 = fmaf(w5.y, t3, fmaf(w5.x, t2, bp1));
            b2 = fmaf(w6.y, t3, fmaf(w6.x, t2, bp2));
            b3 = fmaf(w7.y, t3, fmaf(w7.x, t2, bp3));
        }

        // After chunk 7 (columns 0..31 applied), acc0 is final for every lane
        // (Wsh[l][j]=0 for j>=l, l<32). Store early; STG drain overlaps the
        // remaining 8 chunks.
        if (c == 7) {
            out[row * AD + lane] = acc0;
        }
    }

    // acc1 (dims 32..63) final after the last chunk.
    out[row * AD + lane + 32] = acc1;
}

extern "C" void kernel_launch(void* const* d_in, const int* in_sizes, int n_in,
                              void* d_out, int out_size)
{
    const float* y = (const float*)d_in[0];   // (512, 64)
    const float* a = (const float*)d_in[1];   // (64,)
    const float* W = (const float*)d_in[2];   // (64, 64)
    float* out = (float*)d_out;               // (512, 64)

    arbi_kernel<<<AB / ROWS_PER_BLOCK, NTHREADS>>>(y, a, W, out);
}